// round 10
// baseline (speedup 1.0000x reference)
#include <cuda_runtime.h>
#include <cuda_fp16.h>
#include <math.h>
#include <stdint.h>

#define B_ 64
#define F_ 32
#define S_ 512
#define P_ 96
#define E_ 8
#define H_ 2048
#define T_ (F_*B_)   /* 2048 tokens */
#define ALPHA 10.0f
#define ENT_EPS 1e-8f
#define CV_EPS 1e-10f
#define KS2 2        /* gemm2 k-split */

// ---- scratch (device globals: allocation-free) ----
__device__ __half g_xf[(size_t)T_ * S_];           // 2 MB   token-major x (fp16)
__device__ __half g_w1t[(size_t)E_ * H_ * S_];     // 16.8MB W1^T [e][h][s] (fp16)
__device__ __half g_w2t[(size_t)E_ * P_ * H_];     // 3.1 MB W2^T [e][p][h] (fp16)
__device__ float  g_gates[T_ * E_];                // 64 KB
__device__ __half g_h[(size_t)E_ * T_ * H_];       // 67 MB  gelu(x@W1+b1) (fp16)
__device__ float  g_acc[T_ * P_];                  // 0.8 MB gated accumulator

// ==================================================================
// helpers
// ==================================================================
__device__ __forceinline__ uint32_t smem_u32(const void* p) {
    uint32_t a;
    asm("{ .reg .u64 t; cvta.to.shared.u64 t, %1; cvt.u32.u64 %0, t; }"
        : "=r"(a) : "l"(p));
    return a;
}
__device__ __forceinline__ void cp16(uint32_t saddr, const void* gaddr) {
    asm volatile("cp.async.cg.shared.global [%0], [%1], 16;"
                 :: "r"(saddr), "l"(gaddr) : "memory");
}
#define CP_COMMIT() asm volatile("cp.async.commit_group;" ::: "memory")
#define CP_WAIT2()  asm volatile("cp.async.wait_group 2;" ::: "memory")
#define CP_WAIT3()  asm volatile("cp.async.wait_group 3;" ::: "memory")

__device__ __forceinline__ void mma16(float* d, const uint32_t* a, const uint32_t* b) {
    asm volatile(
        "mma.sync.aligned.m16n8k16.row.col.f32.f16.f16.f32 "
        "{%0,%1,%2,%3}, {%4,%5,%6,%7}, {%8,%9}, {%0,%1,%2,%3};"
        : "+f"(d[0]), "+f"(d[1]), "+f"(d[2]), "+f"(d[3])
        : "r"(a[0]), "r"(a[1]), "r"(a[2]), "r"(a[3]), "r"(b[0]), "r"(b[1]));
}
__device__ __forceinline__ void ldsm4(uint32_t* r, uint32_t addr) {
    asm volatile("ldmatrix.sync.aligned.m8n8.x4.shared.b16 {%0,%1,%2,%3}, [%4];"
                 : "=r"(r[0]), "=r"(r[1]), "=r"(r[2]), "=r"(r[3]) : "r"(addr));
}
__device__ __forceinline__ float gelu_f(float v) {
    return 0.5f * v * (1.f + erff(v * 0.70710678118f));
}

// smem pitch: 40 halves (80 B) per 32-half row -> conflict-free (scalar + ldmatrix)
#define PITCH 40

// ==================================================================
// 1) fused prep + zero + gates:
//    x->g_xf        blocks [0, 1024)
//    W1^T (half2)   blocks [1024, 5120)     64s x 32h tiles
//    W2^T           blocks [5120, 6656)
//    zero g_acc     blocks [6656, 6848)
//    gates          blocks [6848, 7104)     (8 tokens per block)
// ==================================================================
#define PREP_XF_BLKS 1024
#define PREP_W1_BLKS (64 * 8 * E_)      /* 4096 */
#define PREP_W2_BLKS (3 * 64 * E_)      /* 1536 */
#define ZERO_BLKS ((T_ * P_ / 4) / 256) /* 192 */
#define GATES_BLKS (T_ / 8)             /* 256 */
#define PREP_B1 PREP_XF_BLKS
#define PREP_B2 (PREP_B1 + PREP_W1_BLKS)
#define PREP_B3 (PREP_B2 + PREP_W2_BLKS)
#define PREP_B4 (PREP_B3 + ZERO_BLKS)
#define PREP_TOTAL (PREP_B4 + GATES_BLKS)
__global__ void __launch_bounds__(256) prep_all(const float* __restrict__ x,
                                                const float* __restrict__ W1,
                                                const float* __restrict__ W2,
                                                const float* __restrict__ te,
                                                const float* __restrict__ Wg,
                                                const float* __restrict__ bg) {
    __shared__ float tile[64][33];
    __shared__ float s_wg[S_ * 9];
    int bid = blockIdx.x;
    const int tid = threadIdx.x;
    if (bid < PREP_B1) {
        int t = bid * 2 + (tid >> 7);
        int tl = tid & 127;
        int f = t / B_, b = t - f * B_;
        const float4* src = (const float4*)(x + ((size_t)b * F_ + f) * S_);
        float4 v = src[tl];
        __half2* dst = (__half2*)(g_xf + (size_t)t * S_) + tl * 2;
        dst[0] = __floats2half2_rn(v.x, v.y);
        dst[1] = __floats2half2_rn(v.z, v.w);
    } else if (bid < PREP_B2) {
        // W1^T: 64s x 32h tile, vectorized half2 stores
        int i = bid - PREP_B1;
        int e = i >> 9;                  // 512 tiles per expert
        int r = i & 511;
        int h0 = (r & 63) * 32, s0 = (r >> 6) * 64;
        int lx = tid & 31, ly = tid >> 5;
        #pragma unroll
        for (int k = 0; k < 64; k += 8)
            tile[ly + k][lx] = W1[((size_t)e * S_ + s0 + ly + k) * H_ + h0 + lx];
        __syncthreads();
        int sc2 = lx * 2;
        #pragma unroll
        for (int k = 0; k < 32; k += 8) {
            int hr = ly + k;
            __half2 h2 = __floats2half2_rn(tile[sc2][hr], tile[sc2 + 1][hr]);
            *(__half2*)(g_w1t + ((size_t)e * H_ + h0 + hr) * S_ + s0 + sc2) = h2;
        }
    } else if (bid < PREP_B3) {
        int i = bid - PREP_B2;
        int e = i / 192;
        int r = i % 192;
        int p0 = (r % 3) * 32, h0 = (r / 3) * 32;
        int lx = tid & 31, ly = tid >> 5;
        #pragma unroll
        for (int k = 0; k < 32; k += 8)
            tile[ly + k][lx] = W2[((size_t)e * H_ + h0 + ly + k) * P_ + p0 + lx];
        __syncthreads();
        #pragma unroll
        for (int k = 0; k < 32; k += 8)
            g_w2t[((size_t)e * P_ + p0 + ly + k) * H_ + h0 + lx] = __float2half_rn(tile[lx][ly + k]);
    } else if (bid < PREP_B4) {
        int i = bid - PREP_B3;
        ((float4*)g_acc)[i * 256 + tid] = make_float4(0.f, 0.f, 0.f, 0.f);
    } else {
        // ---- gates: 8 tokens, one warp per token ----
        #pragma unroll
        for (int k = 0; k < 16; k++) {
            int idx = tid + 256 * k;     // 4096
            s_wg[(idx >> 3) * 9 + (idx & 7)] = Wg[idx];
        }
        __syncthreads();

        const int w = tid >> 5, lane = tid & 31;
        const int tok = (bid - PREP_B4) * 8 + w;
        const int f = tok / B_, b = tok - f * B_;
        const float* row = te + ((size_t)b * F_ + f) * S_;

        float acc[E_];
        #pragma unroll
        for (int e = 0; e < E_; e++) acc[e] = 0.f;
        #pragma unroll
        for (int c = 0; c < 16; c++) {
            float v = row[c * 32 + lane];
            const float* wp = s_wg + (c * 32 + lane) * 9;
            #pragma unroll
            for (int e = 0; e < E_; e++) acc[e] += v * wp[e];
        }
        #pragma unroll
        for (int e = 0; e < E_; e++)
            #pragma unroll
            for (int o = 16; o > 0; o >>= 1)
                acc[e] += __shfl_xor_sync(0xffffffffu, acc[e], o);

        if (lane == 0) {
            float lg[E_];
            float m1 = -1e30f, m2 = -1e30f;
            #pragma unroll
            for (int i = 0; i < E_; i++) {
                float v = acc[i] + bg[i]; lg[i] = v;
                if (v > m1) { m2 = m1; m1 = v; } else if (v > m2) m2 = v;
            }
            float kth = m2;
            float smv[E_]; float se = 0.f;
            #pragma unroll
            for (int i = 0; i < E_; i++) { smv[i] = expf(lg[i] - m1); se += smv[i]; }
            float inv = 1.f / se;
            float dec[E_]; float mx2 = -1e30f;
            #pragma unroll
            for (int i = 0; i < E_; i++) {
                float smi = smv[i] * inv;
                float d = (lg[i] < kth) ? ALPHA * logf(smi + 1.f)
                                        : ALPHA * (expf(smi) - 1.f);
                dec[i] = d; if (d > mx2) mx2 = d;
            }
            float s2 = 0.f;
            #pragma unroll
            for (int i = 0; i < E_; i++) { dec[i] = expf(dec[i] - mx2); s2 += dec[i]; }
            float inv2 = 1.f / s2;
            #pragma unroll
            for (int i = 0; i < E_; i++) g_gates[tok * E_ + i] = dec[i] * inv2;
        }
    }
}

// ==================================================================
// 4) GEMM1 (HMMA + ldmatrix): h = gelu(Xf @ W1t^T + b1)
//    block 128M x 128N x 32K, 4-stage, 8 warps (2m x 4n), warp 64x32
// ==================================================================
#define G1_B_OFF (128 * PITCH * 2)                  /* bytes */
#define G1_STAGE_B (2 * 128 * PITCH * 2)            /* 20480 bytes */
#define G1_SMEM (4 * G1_STAGE_B)
__global__ void __launch_bounds__(256, 2) gemm1_tc(const float* __restrict__ b1) {
    extern __shared__ __half smh[];
    const int tid = threadIdx.x;
    const int wid = tid >> 5, lane = tid & 31;
    const int g = lane >> 2, q = lane & 3;
    const int e = blockIdx.z;
    const int bm = blockIdx.y * 128, bn = blockIdx.x * 128;
    const int wm = (wid & 1) * 64, wn = (wid >> 1) * 32;
    const uint32_t smb = smem_u32(smh);

    const __half* gA = g_xf + (size_t)bm * S_;
    const __half* gB = g_w1t + ((size_t)e * H_ + bn) * S_;

    uint32_t aoff[4], boff[2];
    {
        const int lrA = lane & 15, lcA = ((lane >> 4) & 1) * 8;
        #pragma unroll
        for (int i = 0; i < 4; i++)
            aoff[i] = (uint32_t)(((wm + i * 16 + lrA) * PITCH + lcA) * 2);
        const int lrB = (lane & 7) + ((lane & 16) >> 1), lcB = lane & 8;
        #pragma unroll
        for (int p = 0; p < 2; p++)
            boff[p] = (uint32_t)(G1_B_OFF + ((wn + p * 16 + lrB) * PITCH + lcB) * 2);
    }

    float acc[4][4][4];
    #pragma unroll
    for (int i = 0; i < 4; i++)
        #pragma unroll
        for (int j = 0; j < 4; j++)
            #pragma unroll
            for (int c = 0; c < 4; c++) acc[i][j][c] = 0.f;

    auto load_stage = [&](int kt, int buf) {
        const uint32_t sA = smb + (uint32_t)buf * G1_STAGE_B;
        const uint32_t sB = sA + G1_B_OFF;
        const int k0 = kt * 32;
        #pragma unroll
        for (int i = 0; i < 2; i++) {
            int idx = tid + 256 * i;
            int r = idx >> 2, c = idx & 3;
            cp16(sA + (uint32_t)r * 80u + (uint32_t)c * 16u,
                 gA + (size_t)r * S_ + k0 + c * 8);
        }
        #pragma unroll
        for (int i = 0; i < 2; i++) {
            int idx = tid + 256 * i;
            int r = idx >> 2, c = idx & 3;
            cp16(sB + (uint32_t)r * 80u + (uint32_t)c * 16u,
                 gB + (size_t)r * S_ + k0 + c * 8);
        }
    };

    const int NKT = S_ / 32;   // 16
    #pragma unroll
    for (int s = 0; s < 3; s++) { load_stage(s, s); CP_COMMIT(); }

    for (int kt = 0; kt < NKT; kt++) {
        CP_WAIT2();
        __syncthreads();
        if (kt + 3 < NKT) load_stage(kt + 3, (kt + 3) & 3);
        CP_COMMIT();
        const uint32_t sbase = smb + (uint32_t)(kt & 3) * G1_STAGE_B;
        #pragma unroll
        for (int ks = 0; ks < 2; ks++) {
            const uint32_t kboff = (uint32_t)(ks * 16 * 2);
            uint32_t a[4][4], bf[2][4];
            #pragma unroll
            for (int i = 0; i < 4; i++) ldsm4(a[i], sbase + aoff[i] + kboff);
            #pragma unroll
            for (int p = 0; p < 2; p++) ldsm4(bf[p], sbase + boff[p] + kboff);
            #pragma unroll
            for (int i = 0; i < 4; i++)
                #pragma unroll
                for (int p = 0; p < 2; p++) {
                    mma16(acc[i][2 * p + 0], a[i], &bf[p][0]);
                    mma16(acc[i][2 * p + 1], a[i], &bf[p][2]);
                }
        }
    }

    const float* bias = b1 + (size_t)e * H_ + bn;
    #pragma unroll
    for (int i = 0; i < 4; i++) {
        int r0 = bm + wm + i * 16 + g;
        #pragma unroll
        for (int j = 0; j < 4; j++) {
            int col = wn + j * 8 + 2 * q;
            float bx = bias[col], by = bias[col + 1];
            __half2 o0 = __floats2half2_rn(gelu_f(acc[i][j][0] + bx),
                                           gelu_f(acc[i][j][1] + by));
            __half2 o1 = __floats2half2_rn(gelu_f(acc[i][j][2] + bx),
                                           gelu_f(acc[i][j][3] + by));
            *(__half2*)(g_h + ((size_t)e * T_ + r0) * H_ + bn + col) = o0;
            *(__half2*)(g_h + ((size_t)e * T_ + r0 + 8) * H_ + bn + col) = o1;
        }
    }
}

// ==================================================================
// 5) GEMM2 (HMMA + ldmatrix, k-split x2): gated RED into g_acc
//    block 128M x 96N x 32K, 5-stage, 8 warps, warp 32x48
// ==================================================================
#define G2_STAGE_H ((128 + 96) * PITCH)
#define G2_B_OFF (128 * PITCH * 2)
#define G2_STAGE_B (G2_STAGE_H * 2)
#define G2_SMEM (5 * G2_STAGE_B)
__global__ void __launch_bounds__(256, 2) gemm2_tc(void) {
    extern __shared__ __half smh[];
    const int tid = threadIdx.x;
    const int wid = tid >> 5, lane = tid & 31;
    const int g = lane >> 2, q = lane & 3;
    const int e = blockIdx.z, ksp = blockIdx.x;
    const int bm = blockIdx.y * 128;
    const int k_base = ksp * (H_ / KS2);
    const int wm = (wid & 3) * 32, wn = (wid >> 2) * 48;
    const uint32_t smb = smem_u32(smh);

    const __half* gA = g_h + ((size_t)e * T_ + bm) * H_ + k_base;
    const __half* gB = g_w2t + (size_t)e * P_ * H_ + k_base;

    uint32_t aoff[2], boff[3];
    {
        const int lrA = lane & 15, lcA = ((lane >> 4) & 1) * 8;
        #pragma unroll
        for (int i = 0; i < 2; i++)
            aoff[i] = (uint32_t)(((wm + i * 16 + lrA) * PITCH + lcA) * 2);
        const int lrB = (lane & 7) + ((lane & 16) >> 1), lcB = lane & 8;
        #pragma unroll
        for (int p = 0; p < 3; p++)
            boff[p] = (uint32_t)(G2_B_OFF + ((wn + p * 16 + lrB) * PITCH + lcB) * 2);
    }

    float acc[2][6][4];
    #pragma unroll
    for (int i = 0; i < 2; i++)
        #pragma unroll
        for (int j = 0; j < 6; j++)
            #pragma unroll
            for (int c = 0; c < 4; c++) acc[i][j][c] = 0.f;

    auto load_stage = [&](int kt, int buf) {
        const uint32_t sA = smb + (uint32_t)buf * G2_STAGE_B;
        const uint32_t sB = sA + G2_B_OFF;
        const int k0 = kt * 32;
        #pragma unroll
        for (int i = 0; i < 2; i++) {
            int idx = tid + 256 * i;
            int r = idx >> 2, c = idx & 3;
            cp16(sA + (uint32_t)r * 80u + (uint32_t)c * 16u,
                 gA + (size_t)r * H_ + k0 + c * 8);
        }
        #pragma unroll
        for (int i = 0; i < 2; i++) {
            int idx = tid + 256 * i;
            if (idx < 384) {
                int r = idx >> 2, c = idx & 3;
                cp16(sB + (uint32_t)r * 80u + (uint32_t)c * 16u,
                     gB + (size_t)r * H_ + k0 + c * 8);
            }
        }
    };

    const int NKT = (H_ / KS2) / 32;   // 32
    #pragma unroll
    for (int s = 0; s < 4; s++) { load_stage(s, s); CP_COMMIT(); }

    int buf = 0, pbuf = 4;
    for (int kt = 0; kt < NKT; kt++) {
        CP_WAIT3();
        __syncthreads();
        if (kt + 4 < NKT) load_stage(kt + 4, pbuf);
        CP_COMMIT();
        const uint32_t sbase = smb + (uint32_t)buf * G2_STAGE_B;
        #pragma unroll
        for (int ks = 0; ks < 2; ks++) {
            const uint32_t kboff = (uint32_t)(ks * 16 * 2);
            uint32_t a[2][4], bf[3][4];
            #pragma unroll
            for (int i = 0; i < 2; i++) ldsm4(a[i], sbase + aoff[i] + kboff);
            #pragma unroll
            for (int p = 0; p < 3; p++) ldsm4(bf[p], sbase + boff[p] + kboff);
            #pragma unroll
            for (int i = 0; i < 2; i++)
                #pragma unroll
                for (int p = 0; p < 3; p++) {
                    mma16(acc[i][2 * p + 0], a[i], &bf[p][0]);
                    mma16(acc[i][2 * p + 1], a[i], &bf[p][2]);
                }
        }
        buf = (buf == 4) ? 0 : buf + 1;
        pbuf = (pbuf == 4) ? 0 : pbuf + 1;
    }

    // epilogue: gate-weighted RED into g_acc (no partial round-trip)
    #pragma unroll
    for (int i = 0; i < 2; i++) {
        int t0 = bm + wm + i * 16 + g;
        float gt0 = g_gates[t0 * E_ + e];
        float gt8 = g_gates[(t0 + 8) * E_ + e];
        #pragma unroll
        for (int j = 0; j < 6; j++) {
            int col = wn + j * 8 + 2 * q;
            atomicAdd(&g_acc[t0 * P_ + col],       gt0 * acc[i][j][0]);
            atomicAdd(&g_acc[t0 * P_ + col + 1],   gt0 * acc[i][j][1]);
            atomicAdd(&g_acc[(t0 + 8) * P_ + col],     gt8 * acc[i][j][2]);
            atomicAdd(&g_acc[(t0 + 8) * P_ + col + 1], gt8 * acc[i][j][3]);
        }
    }
}

// ==================================================================
// 6) combine_final (float4, 128 thr, blocks [0,384)) + losses (block 384)
// ==================================================================
#define COMBINE_BLKS ((T_ * P_ / 4) / 128)   /* 384 */
__global__ void __launch_bounds__(128) combine_final(const float* __restrict__ b2,
                                                     float* __restrict__ out,
                                                     float* __restrict__ out_scalars) {
    if (blockIdx.x < COMBINE_BLKS) {
        int idx = (blockIdx.x * 128 + threadIdx.x) * 4;
        int t = idx / P_, p = idx - t * P_;
        int f = t / B_, b = t - f * B_;
        float4 r = *(const float4*)(g_acc + t * P_ + p);
        #pragma unroll
        for (int e = 0; e < E_; e++) {
            float gt = g_gates[t * E_ + e];
            float4 bv = *(const float4*)(b2 + e * P_ + p);
            r.x += gt * bv.x; r.y += gt * bv.y;
            r.z += gt * bv.z; r.w += gt * bv.w;
        }
        *(float4*)(out + ((size_t)b * F_ + f) * P_ + p) = r;
        return;
    }
    // losses block (128 threads, 2 (f,e) pairs each)
    __shared__ float gsum[F_][E_];
    __shared__ float cvf[F_], entf[F_];
    int tid = threadIdx.x;
    #pragma unroll
    for (int z = 0; z < 2; z++) {
        int id = tid + 128 * z;
        int f = id >> 3, e = id & 7;
        float s = 0.f;
        for (int b = 0; b < B_; b++) s += g_gates[(f * B_ + b) * E_ + e];
        gsum[f][e] = s;
    }
    __syncthreads();
    if (tid < F_) {
        float mean = 0.f;
        #pragma unroll
        for (int i = 0; i < E_; i++) mean += gsum[tid][i];
        mean *= (1.f / E_);
        float ss = 0.f;
        #pragma unroll
        for (int i = 0; i < E_; i++) { float d = gsum[tid][i] - mean; ss += d * d; }
        float var = ss * (float)P_ / (float)(E_ * P_ - 1);
        cvf[tid] = var / (mean * mean + CV_EPS);
        float ent = 0.f;
        #pragma unroll
        for (int i = 0; i < E_; i++) {
            float g = gsum[tid][i] * (1.f / B_);
            ent += -g * logf(g + ENT_EPS);
        }
        entf[tid] = ent * (1.f / E_);
    }
    __syncthreads();
    if (tid == 0) {
        float a = 0.f, c = 0.f;
        for (int i = 0; i < F_; i++) { a += cvf[i]; c += entf[i]; }
        out_scalars[0] = a;
        out_scalars[1] = c;
    }
}

// ==================================================================
extern "C" void kernel_launch(void* const* d_in, const int* in_sizes, int n_in,
                              void* d_out, int out_size) {
    const float* x  = (const float*)d_in[0];
    const float* te = (const float*)d_in[1];
    const float* Wg = (const float*)d_in[2];
    const float* bg = (const float*)d_in[3];
    const float* W1 = (const float*)d_in[4];
    const float* b1 = (const float*)d_in[5];
    const float* W2 = (const float*)d_in[6];
    const float* b2 = (const float*)d_in[7];
    float* out = (float*)d_out;

    cudaFuncSetAttribute(gemm1_tc, cudaFuncAttributeMaxDynamicSharedMemorySize, G1_SMEM);
    cudaFuncSetAttribute(gemm2_tc, cudaFuncAttributeMaxDynamicSharedMemorySize, G2_SMEM);

    prep_all<<<PREP_TOTAL, 256>>>(x, W1, W2, te, Wg, bg);
    gemm1_tc<<<dim3(H_ / 128, T_ / 128, E_), 256, G1_SMEM>>>(b1);
    gemm2_tc<<<dim3(KS2, T_ / 128, E_), 256, G2_SMEM>>>();
    combine_final<<<COMBINE_BLKS + 1, 128>>>(b2, out, out + (out_size - 2));
}

// round 11
// speedup vs baseline: 1.0417x; 1.0417x over previous
#include <cuda_runtime.h>
#include <cuda_fp16.h>
#include <math.h>
#include <stdint.h>

#define B_ 64
#define F_ 32
#define S_ 512
#define P_ 96
#define E_ 8
#define H_ 2048
#define T_ (F_*B_)   /* 2048 tokens */
#define ALPHA 10.0f
#define ENT_EPS 1e-8f
#define CV_EPS 1e-10f
#define KS2 2        /* gemm2 k-split */

// ---- scratch (device globals: allocation-free) ----
__device__ __half g_xf[(size_t)T_ * S_];           // 2 MB   token-major x (fp16)
__device__ __half g_w1t[(size_t)E_ * H_ * S_];     // 16.8MB W1^T [e][h][s] (fp16)
__device__ __half g_w2t[(size_t)E_ * P_ * H_];     // 3.1 MB W2^T [e][p][h] (fp16)
__device__ float  g_gates[T_ * E_];                // 64 KB
__device__ __half g_h[(size_t)E_ * T_ * H_];       // 67 MB  gelu(x@W1+b1) (fp16)
__device__ float  g_acc[T_ * P_];                  // 0.8 MB gated accumulator

// ==================================================================
// helpers
// ==================================================================
__device__ __forceinline__ uint32_t smem_u32(const void* p) {
    uint32_t a;
    asm("{ .reg .u64 t; cvta.to.shared.u64 t, %1; cvt.u32.u64 %0, t; }"
        : "=r"(a) : "l"(p));
    return a;
}
__device__ __forceinline__ void cp16(uint32_t saddr, const void* gaddr) {
    asm volatile("cp.async.cg.shared.global [%0], [%1], 16;"
                 :: "r"(saddr), "l"(gaddr) : "memory");
}
#define CP_COMMIT() asm volatile("cp.async.commit_group;" ::: "memory")
#define CP_WAIT2()  asm volatile("cp.async.wait_group 2;" ::: "memory")
#define CP_WAIT3()  asm volatile("cp.async.wait_group 3;" ::: "memory")

__device__ __forceinline__ void mma16(float* d, const uint32_t* a, const uint32_t* b) {
    asm volatile(
        "mma.sync.aligned.m16n8k16.row.col.f32.f16.f16.f32 "
        "{%0,%1,%2,%3}, {%4,%5,%6,%7}, {%8,%9}, {%0,%1,%2,%3};"
        : "+f"(d[0]), "+f"(d[1]), "+f"(d[2]), "+f"(d[3])
        : "r"(a[0]), "r"(a[1]), "r"(a[2]), "r"(a[3]), "r"(b[0]), "r"(b[1]));
}
__device__ __forceinline__ void ldsm4(uint32_t* r, uint32_t addr) {
    asm volatile("ldmatrix.sync.aligned.m8n8.x4.shared.b16 {%0,%1,%2,%3}, [%4];"
                 : "=r"(r[0]), "=r"(r[1]), "=r"(r[2]), "=r"(r[3]) : "r"(addr));
}
__device__ __forceinline__ float gelu_f(float v) {
    return 0.5f * v * (1.f + erff(v * 0.70710678118f));
}

// smem pitch: 40 halves (80 B) per 32-half row -> conflict-free (scalar + ldmatrix)
#define PITCH 40

// ==================================================================
// 1) prep: x->g_xf (blocks [0,1024)), W1^T half2 (blocks [1024,5120))
// ==================================================================
#define PREP_XF_BLKS 1024
#define PREP_W1_BLKS (64 * 8 * E_)      /* 4096 */
#define PREP_TOTAL (PREP_XF_BLKS + PREP_W1_BLKS)
__global__ void __launch_bounds__(256) prep_xw(const float* __restrict__ x,
                                               const float* __restrict__ W1) {
    __shared__ float tile[64][33];
    int bid = blockIdx.x;
    const int tid = threadIdx.x;
    if (bid < PREP_XF_BLKS) {
        int t = bid * 2 + (tid >> 7);
        int tl = tid & 127;
        int f = t / B_, b = t - f * B_;
        const float4* src = (const float4*)(x + ((size_t)b * F_ + f) * S_);
        float4 v = src[tl];
        __half2* dst = (__half2*)(g_xf + (size_t)t * S_) + tl * 2;
        dst[0] = __floats2half2_rn(v.x, v.y);
        dst[1] = __floats2half2_rn(v.z, v.w);
    } else {
        int i = bid - PREP_XF_BLKS;
        int e = i >> 9;                  // 512 tiles per expert
        int r = i & 511;
        int h0 = (r & 63) * 32, s0 = (r >> 6) * 64;
        int lx = tid & 31, ly = tid >> 5;
        #pragma unroll
        for (int k = 0; k < 64; k += 8)
            tile[ly + k][lx] = W1[((size_t)e * S_ + s0 + ly + k) * H_ + h0 + lx];
        __syncthreads();
        int sc2 = lx * 2;
        #pragma unroll
        for (int k = 0; k < 32; k += 8) {
            int hr = ly + k;
            __half2 h2 = __floats2half2_rn(tile[sc2][hr], tile[sc2 + 1][hr]);
            *(__half2*)(g_w1t + ((size_t)e * H_ + h0 + hr) * S_ + s0 + sc2) = h2;
        }
    }
}

// ==================================================================
// 2) GEMM1 fused launch (1D grid):
//    [0, 2048)      gemm1 HMMA tiles (128x128x32, 4-stage, 8 warps)
//    [2048, 3584)   W2^T transpose
//    [3584, 3776)   zero g_acc
//    [3776, 4032)   gates (8 tokens per block)
// ==================================================================
#define G1_TILES 2048
#define G1_W2_END (G1_TILES + 1536)
#define G1_ZERO_END (G1_W2_END + 192)
#define G1_TOTAL (G1_ZERO_END + 256)
#define G1_B_OFF (128 * PITCH * 2)                  /* bytes */
#define G1_STAGE_B (2 * 128 * PITCH * 2)            /* 20480 bytes */
#define G1_SMEM (4 * G1_STAGE_B)
__global__ void __launch_bounds__(256, 2) gemm1_fused(const float* __restrict__ b1,
                                                      const float* __restrict__ W2,
                                                      const float* __restrict__ te,
                                                      const float* __restrict__ Wg,
                                                      const float* __restrict__ bg) {
    extern __shared__ __half smh[];
    const int bid = blockIdx.x;
    const int tid = threadIdx.x;

    if (bid >= G1_TILES) {
        if (bid < G1_W2_END) {
            // ---- W2^T ----
            float* tile = (float*)smh;               // [32][33]
            int i = bid - G1_TILES;
            int e = i / 192, r = i % 192;
            int p0 = (r % 3) * 32, h0 = (r / 3) * 32;
            int lx = tid & 31, ly = tid >> 5;
            #pragma unroll
            for (int k = 0; k < 32; k += 8)
                tile[(ly + k) * 33 + lx] = W2[((size_t)e * H_ + h0 + ly + k) * P_ + p0 + lx];
            __syncthreads();
            #pragma unroll
            for (int k = 0; k < 32; k += 8)
                g_w2t[((size_t)e * P_ + p0 + ly + k) * H_ + h0 + lx] =
                    __float2half_rn(tile[lx * 33 + ly + k]);
        } else if (bid < G1_ZERO_END) {
            int i = bid - G1_W2_END;
            ((float4*)g_acc)[i * 256 + tid] = make_float4(0.f, 0.f, 0.f, 0.f);
        } else {
            // ---- gates: 8 tokens, one warp per token ----
            float* s_wg = (float*)smh;               // [512][9] = 18 KB
            #pragma unroll
            for (int k = 0; k < 16; k++) {
                int idx = tid + 256 * k;             // 4096
                s_wg[(idx >> 3) * 9 + (idx & 7)] = Wg[idx];
            }
            __syncthreads();

            const int w = tid >> 5, lane = tid & 31;
            const int tok = (bid - G1_ZERO_END) * 8 + w;
            const int f = tok / B_, b = tok - f * B_;
            const float* row = te + ((size_t)b * F_ + f) * S_;

            float acc[E_];
            #pragma unroll
            for (int e = 0; e < E_; e++) acc[e] = 0.f;
            #pragma unroll
            for (int c = 0; c < 16; c++) {
                float v = row[c * 32 + lane];
                const float* wp = s_wg + (c * 32 + lane) * 9;
                #pragma unroll
                for (int e = 0; e < E_; e++) acc[e] += v * wp[e];
            }
            #pragma unroll
            for (int e = 0; e < E_; e++)
                #pragma unroll
                for (int o = 16; o > 0; o >>= 1)
                    acc[e] += __shfl_xor_sync(0xffffffffu, acc[e], o);

            if (lane == 0) {
                float lg[E_];
                float m1 = -1e30f, m2 = -1e30f;
                #pragma unroll
                for (int i = 0; i < E_; i++) {
                    float v = acc[i] + bg[i]; lg[i] = v;
                    if (v > m1) { m2 = m1; m1 = v; } else if (v > m2) m2 = v;
                }
                float kth = m2;
                float smv[E_]; float se = 0.f;
                #pragma unroll
                for (int i = 0; i < E_; i++) { smv[i] = expf(lg[i] - m1); se += smv[i]; }
                float inv = 1.f / se;
                float dec[E_]; float mx2 = -1e30f;
                #pragma unroll
                for (int i = 0; i < E_; i++) {
                    float smi = smv[i] * inv;
                    float d = (lg[i] < kth) ? ALPHA * logf(smi + 1.f)
                                            : ALPHA * (expf(smi) - 1.f);
                    dec[i] = d; if (d > mx2) mx2 = d;
                }
                float s2 = 0.f;
                #pragma unroll
                for (int i = 0; i < E_; i++) { dec[i] = expf(dec[i] - mx2); s2 += dec[i]; }
                float inv2 = 1.f / s2;
                #pragma unroll
                for (int i = 0; i < E_; i++) g_gates[tok * E_ + i] = dec[i] * inv2;
            }
        }
        return;
    }

    // ---- gemm1 tile ----
    const int wid = tid >> 5, lane = tid & 31;
    const int g = lane >> 2, q = lane & 3;
    const int e = bid >> 8;
    const int r8 = bid & 255;
    const int bm = (r8 >> 4) * 128, bn = (r8 & 15) * 128;
    const int wm = (wid & 1) * 64, wn = (wid >> 1) * 32;
    const uint32_t smb = smem_u32(smh);

    const __half* gA = g_xf + (size_t)bm * S_;
    const __half* gB = g_w1t + ((size_t)e * H_ + bn) * S_;

    uint32_t aoff[4], boff[2];
    {
        const int lrA = lane & 15, lcA = ((lane >> 4) & 1) * 8;
        #pragma unroll
        for (int i = 0; i < 4; i++)
            aoff[i] = (uint32_t)(((wm + i * 16 + lrA) * PITCH + lcA) * 2);
        const int lrB = (lane & 7) + ((lane & 16) >> 1), lcB = lane & 8;
        #pragma unroll
        for (int p = 0; p < 2; p++)
            boff[p] = (uint32_t)(G1_B_OFF + ((wn + p * 16 + lrB) * PITCH + lcB) * 2);
    }

    float acc[4][4][4];
    #pragma unroll
    for (int i = 0; i < 4; i++)
        #pragma unroll
        for (int j = 0; j < 4; j++)
            #pragma unroll
            for (int c = 0; c < 4; c++) acc[i][j][c] = 0.f;

    auto load_stage = [&](int kt, int buf) {
        const uint32_t sA = smb + (uint32_t)buf * G1_STAGE_B;
        const uint32_t sB = sA + G1_B_OFF;
        const int k0 = kt * 32;
        #pragma unroll
        for (int i = 0; i < 2; i++) {
            int idx = tid + 256 * i;
            int r = idx >> 2, c = idx & 3;
            cp16(sA + (uint32_t)r * 80u + (uint32_t)c * 16u,
                 gA + (size_t)r * S_ + k0 + c * 8);
        }
        #pragma unroll
        for (int i = 0; i < 2; i++) {
            int idx = tid + 256 * i;
            int r = idx >> 2, c = idx & 3;
            cp16(sB + (uint32_t)r * 80u + (uint32_t)c * 16u,
                 gB + (size_t)r * S_ + k0 + c * 8);
        }
    };

    const int NKT = S_ / 32;   // 16
    #pragma unroll
    for (int s = 0; s < 3; s++) { load_stage(s, s); CP_COMMIT(); }

    for (int kt = 0; kt < NKT; kt++) {
        CP_WAIT2();
        __syncthreads();
        if (kt + 3 < NKT) load_stage(kt + 3, (kt + 3) & 3);
        CP_COMMIT();
        const uint32_t sbase = smb + (uint32_t)(kt & 3) * G1_STAGE_B;
        #pragma unroll
        for (int ks = 0; ks < 2; ks++) {
            const uint32_t kboff = (uint32_t)(ks * 16 * 2);
            uint32_t a[4][4], bf[2][4];
            #pragma unroll
            for (int i = 0; i < 4; i++) ldsm4(a[i], sbase + aoff[i] + kboff);
            #pragma unroll
            for (int p = 0; p < 2; p++) ldsm4(bf[p], sbase + boff[p] + kboff);
            #pragma unroll
            for (int i = 0; i < 4; i++)
                #pragma unroll
                for (int p = 0; p < 2; p++) {
                    mma16(acc[i][2 * p + 0], a[i], &bf[p][0]);
                    mma16(acc[i][2 * p + 1], a[i], &bf[p][2]);
                }
        }
    }

    const float* bias = b1 + (size_t)e * H_ + bn;
    #pragma unroll
    for (int i = 0; i < 4; i++) {
        int r0 = bm + wm + i * 16 + g;
        #pragma unroll
        for (int j = 0; j < 4; j++) {
            int col = wn + j * 8 + 2 * q;
            float bx = bias[col], by = bias[col + 1];
            __half2 o0 = __floats2half2_rn(gelu_f(acc[i][j][0] + bx),
                                           gelu_f(acc[i][j][1] + by));
            __half2 o1 = __floats2half2_rn(gelu_f(acc[i][j][2] + bx),
                                           gelu_f(acc[i][j][3] + by));
            *(__half2*)(g_h + ((size_t)e * T_ + r0) * H_ + bn + col) = o0;
            *(__half2*)(g_h + ((size_t)e * T_ + r0 + 8) * H_ + bn + col) = o1;
        }
    }
}

// ==================================================================
// 3) GEMM2 fused launch (1D grid 257):
//    [0,256)  gemm2 tiles (128x96x32, 5-stage, k-split x2, gated RED)
//    256      losses (parallelized)
// ==================================================================
#define G2_STAGE_H ((128 + 96) * PITCH)
#define G2_B_OFF (128 * PITCH * 2)
#define G2_STAGE_B (G2_STAGE_H * 2)
#define G2_SMEM (5 * G2_STAGE_B)
__global__ void __launch_bounds__(256, 2) gemm2_fused(float* __restrict__ out_scalars) {
    extern __shared__ __half smh[];
    const int bid = blockIdx.x;
    const int tid = threadIdx.x;

    if (bid == 256) {
        // ---- losses: 256 threads, one (f,e) pair each, MLP-unrolled ----
        __shared__ float gsum[F_][E_];
        __shared__ float cvf[F_], entf[F_];
        int f = tid >> 3, e = tid & 7;
        float s0 = 0.f, s1 = 0.f, s2 = 0.f, s3 = 0.f;
        #pragma unroll
        for (int b = 0; b < B_; b += 4) {
            s0 += g_gates[(f * B_ + b + 0) * E_ + e];
            s1 += g_gates[(f * B_ + b + 1) * E_ + e];
            s2 += g_gates[(f * B_ + b + 2) * E_ + e];
            s3 += g_gates[(f * B_ + b + 3) * E_ + e];
        }
        gsum[f][e] = (s0 + s1) + (s2 + s3);
        __syncthreads();
        if (tid < F_) {
            float mean = 0.f;
            #pragma unroll
            for (int i = 0; i < E_; i++) mean += gsum[tid][i];
            mean *= (1.f / E_);
            float ss = 0.f;
            #pragma unroll
            for (int i = 0; i < E_; i++) { float d = gsum[tid][i] - mean; ss += d * d; }
            float var = ss * (float)P_ / (float)(E_ * P_ - 1);
            cvf[tid] = var / (mean * mean + CV_EPS);
            float ent = 0.f;
            #pragma unroll
            for (int i = 0; i < E_; i++) {
                float g = gsum[tid][i] * (1.f / B_);
                ent += -g * logf(g + ENT_EPS);
            }
            entf[tid] = ent * (1.f / E_);
        }
        __syncthreads();
        if (tid == 0) {
            float a = 0.f, c = 0.f;
            for (int i = 0; i < F_; i++) { a += cvf[i]; c += entf[i]; }
            out_scalars[0] = a;
            out_scalars[1] = c;
        }
        return;
    }

    // ---- gemm2 tile ----
    const int wid = tid >> 5, lane = tid & 31;
    const int g = lane >> 2, q = lane & 3;
    const int ksp = bid & 1;
    const int bm = ((bid >> 1) & 15) * 128;
    const int e = bid >> 5;
    const int k_base = ksp * (H_ / KS2);
    const int wm = (wid & 3) * 32, wn = (wid >> 2) * 48;
    const uint32_t smb = smem_u32(smh);

    const __half* gA = g_h + ((size_t)e * T_ + bm) * H_ + k_base;
    const __half* gB = g_w2t + (size_t)e * P_ * H_ + k_base;

    uint32_t aoff[2], boff[3];
    {
        const int lrA = lane & 15, lcA = ((lane >> 4) & 1) * 8;
        #pragma unroll
        for (int i = 0; i < 2; i++)
            aoff[i] = (uint32_t)(((wm + i * 16 + lrA) * PITCH + lcA) * 2);
        const int lrB = (lane & 7) + ((lane & 16) >> 1), lcB = lane & 8;
        #pragma unroll
        for (int p = 0; p < 3; p++)
            boff[p] = (uint32_t)(G2_B_OFF + ((wn + p * 16 + lrB) * PITCH + lcB) * 2);
    }

    float acc[2][6][4];
    #pragma unroll
    for (int i = 0; i < 2; i++)
        #pragma unroll
        for (int j = 0; j < 6; j++)
            #pragma unroll
            for (int c = 0; c < 4; c++) acc[i][j][c] = 0.f;

    auto load_stage = [&](int kt, int buf) {
        const uint32_t sA = smb + (uint32_t)buf * G2_STAGE_B;
        const uint32_t sB = sA + G2_B_OFF;
        const int k0 = kt * 32;
        #pragma unroll
        for (int i = 0; i < 2; i++) {
            int idx = tid + 256 * i;
            int r = idx >> 2, c = idx & 3;
            cp16(sA + (uint32_t)r * 80u + (uint32_t)c * 16u,
                 gA + (size_t)r * H_ + k0 + c * 8);
        }
        #pragma unroll
        for (int i = 0; i < 2; i++) {
            int idx = tid + 256 * i;
            if (idx < 384) {
                int r = idx >> 2, c = idx & 3;
                cp16(sB + (uint32_t)r * 80u + (uint32_t)c * 16u,
                     gB + (size_t)r * H_ + k0 + c * 8);
            }
        }
    };

    const int NKT = (H_ / KS2) / 32;   // 32
    #pragma unroll
    for (int s = 0; s < 4; s++) { load_stage(s, s); CP_COMMIT(); }

    int buf = 0, pbuf = 4;
    for (int kt = 0; kt < NKT; kt++) {
        CP_WAIT3();
        __syncthreads();
        if (kt + 4 < NKT) load_stage(kt + 4, pbuf);
        CP_COMMIT();
        const uint32_t sbase = smb + (uint32_t)buf * G2_STAGE_B;
        #pragma unroll
        for (int ks = 0; ks < 2; ks++) {
            const uint32_t kboff = (uint32_t)(ks * 16 * 2);
            uint32_t a[2][4], bf[3][4];
            #pragma unroll
            for (int i = 0; i < 2; i++) ldsm4(a[i], sbase + aoff[i] + kboff);
            #pragma unroll
            for (int p = 0; p < 3; p++) ldsm4(bf[p], sbase + boff[p] + kboff);
            #pragma unroll
            for (int i = 0; i < 2; i++)
                #pragma unroll
                for (int p = 0; p < 3; p++) {
                    mma16(acc[i][2 * p + 0], a[i], &bf[p][0]);
                    mma16(acc[i][2 * p + 1], a[i], &bf[p][2]);
                }
        }
        buf = (buf == 4) ? 0 : buf + 1;
        pbuf = (pbuf == 4) ? 0 : pbuf + 1;
    }

    // epilogue: gate-weighted RED into g_acc
    #pragma unroll
    for (int i = 0; i < 2; i++) {
        int t0 = bm + wm + i * 16 + g;
        float gt0 = g_gates[t0 * E_ + e];
        float gt8 = g_gates[(t0 + 8) * E_ + e];
        #pragma unroll
        for (int j = 0; j < 6; j++) {
            int col = wn + j * 8 + 2 * q;
            atomicAdd(&g_acc[t0 * P_ + col],       gt0 * acc[i][j][0]);
            atomicAdd(&g_acc[t0 * P_ + col + 1],   gt0 * acc[i][j][1]);
            atomicAdd(&g_acc[(t0 + 8) * P_ + col],     gt8 * acc[i][j][2]);
            atomicAdd(&g_acc[(t0 + 8) * P_ + col + 1], gt8 * acc[i][j][3]);
        }
    }
}

// ==================================================================
// 4) combine_final: pure elementwise, float4, 384 blocks x 128 thr
// ==================================================================
#define COMBINE_BLKS ((T_ * P_ / 4) / 128)   /* 384 */
__global__ void __launch_bounds__(128) combine_final(const float* __restrict__ b2,
                                                     float* __restrict__ out) {
    int idx = (blockIdx.x * 128 + threadIdx.x) * 4;
    int t = idx / P_, p = idx - t * P_;
    int f = t / B_, b = t - f * B_;
    float4 r = *(const float4*)(g_acc + t * P_ + p);
    #pragma unroll
    for (int e = 0; e < E_; e++) {
        float gt = g_gates[t * E_ + e];
        float4 bv = *(const float4*)(b2 + e * P_ + p);
        r.x += gt * bv.x; r.y += gt * bv.y;
        r.z += gt * bv.z; r.w += gt * bv.w;
    }
    *(float4*)(out + ((size_t)b * F_ + f) * P_ + p) = r;
}

// ==================================================================
extern "C" void kernel_launch(void* const* d_in, const int* in_sizes, int n_in,
                              void* d_out, int out_size) {
    const float* x  = (const float*)d_in[0];
    const float* te = (const float*)d_in[1];
    const float* Wg = (const float*)d_in[2];
    const float* bg = (const float*)d_in[3];
    const float* W1 = (const float*)d_in[4];
    const float* b1 = (const float*)d_in[5];
    const float* W2 = (const float*)d_in[6];
    const float* b2 = (const float*)d_in[7];
    float* out = (float*)d_out;

    cudaFuncSetAttribute(gemm1_fused, cudaFuncAttributeMaxDynamicSharedMemorySize, G1_SMEM);
    cudaFuncSetAttribute(gemm2_fused, cudaFuncAttributeMaxDynamicSharedMemorySize, G2_SMEM);

    prep_xw<<<PREP_TOTAL, 256>>>(x, W1);
    gemm1_fused<<<G1_TOTAL, 256, G1_SMEM>>>(b1, W2, te, Wg, bg);
    gemm2_fused<<<257, 256, G2_SMEM>>>(out + (out_size - 2));
    combine_final<<<COMBINE_BLKS, 128>>>(b2, out);
}

// round 12
// speedup vs baseline: 1.0527x; 1.0106x over previous
#include <cuda_runtime.h>
#include <cuda_fp16.h>
#include <math.h>
#include <stdint.h>

#define B_ 64
#define F_ 32
#define S_ 512
#define P_ 96
#define E_ 8
#define H_ 2048
#define T_ (F_*B_)   /* 2048 tokens */
#define ALPHA 10.0f
#define ENT_EPS 1e-8f
#define CV_EPS 1e-10f
#define KS2 2        /* gemm2 k-split */

// ---- scratch (device globals: allocation-free) ----
__device__ __half g_xf[(size_t)T_ * S_];           // 2 MB   token-major x (fp16)
__device__ __half g_w1t[(size_t)E_ * H_ * S_];     // 16.8MB W1^T [e][h][s] (fp16)
__device__ __half g_w2t[(size_t)E_ * P_ * H_];     // 3.1 MB W2^T [e][p][h] (fp16)
__device__ float  g_gates[T_ * E_];                // 64 KB
__device__ __half g_h[(size_t)E_ * T_ * H_];       // 67 MB  gelu(x@W1+b1) (fp16)

// ==================================================================
// helpers
// ==================================================================
__device__ __forceinline__ uint32_t smem_u32(const void* p) {
    uint32_t a;
    asm("{ .reg .u64 t; cvta.to.shared.u64 t, %1; cvt.u32.u64 %0, t; }"
        : "=r"(a) : "l"(p));
    return a;
}
__device__ __forceinline__ void cp16(uint32_t saddr, const void* gaddr) {
    asm volatile("cp.async.cg.shared.global [%0], [%1], 16;"
                 :: "r"(saddr), "l"(gaddr) : "memory");
}
#define CP_COMMIT() asm volatile("cp.async.commit_group;" ::: "memory")
#define CP_WAIT2()  asm volatile("cp.async.wait_group 2;" ::: "memory")
#define CP_WAIT3()  asm volatile("cp.async.wait_group 3;" ::: "memory")

__device__ __forceinline__ void mma16(float* d, const uint32_t* a, const uint32_t* b) {
    asm volatile(
        "mma.sync.aligned.m16n8k16.row.col.f32.f16.f16.f32 "
        "{%0,%1,%2,%3}, {%4,%5,%6,%7}, {%8,%9}, {%0,%1,%2,%3};"
        : "+f"(d[0]), "+f"(d[1]), "+f"(d[2]), "+f"(d[3])
        : "r"(a[0]), "r"(a[1]), "r"(a[2]), "r"(a[3]), "r"(b[0]), "r"(b[1]));
}
__device__ __forceinline__ void ldsm4(uint32_t* r, uint32_t addr) {
    asm volatile("ldmatrix.sync.aligned.m8n8.x4.shared.b16 {%0,%1,%2,%3}, [%4];"
                 : "=r"(r[0]), "=r"(r[1]), "=r"(r[2]), "=r"(r[3]) : "r"(addr));
}
__device__ __forceinline__ float gelu_f(float v) {
    return 0.5f * v * (1.f + erff(v * 0.70710678118f));
}

// smem pitch: 40 halves (80 B) per 32-half row -> conflict-free (scalar + ldmatrix)
#define PITCH 40

// ==================================================================
// 1) prep: x->g_xf (blocks [0,1024)), W1^T half2 (blocks [1024,5120))
// ==================================================================
#define PREP_XF_BLKS 1024
#define PREP_W1_BLKS (64 * 8 * E_)      /* 4096 */
#define PREP_TOTAL (PREP_XF_BLKS + PREP_W1_BLKS)
__global__ void __launch_bounds__(256) prep_xw(const float* __restrict__ x,
                                               const float* __restrict__ W1) {
    __shared__ float tile[64][33];
    int bid = blockIdx.x;
    const int tid = threadIdx.x;
    if (bid < PREP_XF_BLKS) {
        int t = bid * 2 + (tid >> 7);
        int tl = tid & 127;
        int f = t / B_, b = t - f * B_;
        const float4* src = (const float4*)(x + ((size_t)b * F_ + f) * S_);
        float4 v = src[tl];
        __half2* dst = (__half2*)(g_xf + (size_t)t * S_) + tl * 2;
        dst[0] = __floats2half2_rn(v.x, v.y);
        dst[1] = __floats2half2_rn(v.z, v.w);
    } else {
        int i = bid - PREP_XF_BLKS;
        int e = i >> 9;                  // 512 tiles per expert
        int r = i & 511;
        int h0 = (r & 63) * 32, s0 = (r >> 6) * 64;
        int lx = tid & 31, ly = tid >> 5;
        #pragma unroll
        for (int k = 0; k < 64; k += 8)
            tile[ly + k][lx] = W1[((size_t)e * S_ + s0 + ly + k) * H_ + h0 + lx];
        __syncthreads();
        int sc2 = lx * 2;
        #pragma unroll
        for (int k = 0; k < 32; k += 8) {
            int hr = ly + k;
            __half2 h2 = __floats2half2_rn(tile[sc2][hr], tile[sc2 + 1][hr]);
            *(__half2*)(g_w1t + ((size_t)e * H_ + h0 + hr) * S_ + s0 + sc2) = h2;
        }
    }
}

// ==================================================================
// 2) GEMM1 fused launch (1D grid):
//    [0, 2048)      gemm1 HMMA tiles (128x128x32, 4-stage, 8 warps)
//    [2048, 3584)   W2^T transpose
//    [3584, 3776)   zero out[0, T*P)
//    [3776, 4032)   gates (8 tokens per block)
// ==================================================================
#define G1_TILES 2048
#define G1_W2_END (G1_TILES + 1536)
#define G1_ZERO_END (G1_W2_END + 192)
#define G1_TOTAL (G1_ZERO_END + 256)
#define G1_B_OFF (128 * PITCH * 2)                  /* bytes */
#define G1_STAGE_B (2 * 128 * PITCH * 2)            /* 20480 bytes */
#define G1_SMEM (4 * G1_STAGE_B)
__global__ void __launch_bounds__(256, 2) gemm1_fused(const float* __restrict__ b1,
                                                      const float* __restrict__ W2,
                                                      const float* __restrict__ te,
                                                      const float* __restrict__ Wg,
                                                      const float* __restrict__ bg,
                                                      float* __restrict__ out) {
    extern __shared__ __half smh[];
    const int bid = blockIdx.x;
    const int tid = threadIdx.x;

    if (bid >= G1_TILES) {
        if (bid < G1_W2_END) {
            // ---- W2^T ----
            float* tile = (float*)smh;               // [32][33]
            int i = bid - G1_TILES;
            int e = i / 192, r = i % 192;
            int p0 = (r % 3) * 32, h0 = (r / 3) * 32;
            int lx = tid & 31, ly = tid >> 5;
            #pragma unroll
            for (int k = 0; k < 32; k += 8)
                tile[(ly + k) * 33 + lx] = W2[((size_t)e * H_ + h0 + ly + k) * P_ + p0 + lx];
            __syncthreads();
            #pragma unroll
            for (int k = 0; k < 32; k += 8)
                g_w2t[((size_t)e * P_ + p0 + ly + k) * H_ + h0 + lx] =
                    __float2half_rn(tile[lx * 33 + ly + k]);
        } else if (bid < G1_ZERO_END) {
            int i = bid - G1_W2_END;
            ((float4*)out)[i * 256 + tid] = make_float4(0.f, 0.f, 0.f, 0.f);
        } else {
            // ---- gates: 8 tokens, one warp per token ----
            float* s_wg = (float*)smh;               // [512][9] = 18 KB
            #pragma unroll
            for (int k = 0; k < 16; k++) {
                int idx = tid + 256 * k;             // 4096
                s_wg[(idx >> 3) * 9 + (idx & 7)] = Wg[idx];
            }
            __syncthreads();

            const int w = tid >> 5, lane = tid & 31;
            const int tok = (bid - G1_ZERO_END) * 8 + w;
            const int f = tok / B_, b = tok - f * B_;
            const float* row = te + ((size_t)b * F_ + f) * S_;

            float acc[E_];
            #pragma unroll
            for (int e = 0; e < E_; e++) acc[e] = 0.f;
            #pragma unroll
            for (int c = 0; c < 16; c++) {
                float v = row[c * 32 + lane];
                const float* wp = s_wg + (c * 32 + lane) * 9;
                #pragma unroll
                for (int e = 0; e < E_; e++) acc[e] += v * wp[e];
            }
            #pragma unroll
            for (int e = 0; e < E_; e++)
                #pragma unroll
                for (int o = 16; o > 0; o >>= 1)
                    acc[e] += __shfl_xor_sync(0xffffffffu, acc[e], o);

            if (lane == 0) {
                float lg[E_];
                float m1 = -1e30f, m2 = -1e30f;
                #pragma unroll
                for (int i = 0; i < E_; i++) {
                    float v = acc[i] + bg[i]; lg[i] = v;
                    if (v > m1) { m2 = m1; m1 = v; } else if (v > m2) m2 = v;
                }
                float kth = m2;
                float smv[E_]; float se = 0.f;
                #pragma unroll
                for (int i = 0; i < E_; i++) { smv[i] = expf(lg[i] - m1); se += smv[i]; }
                float inv = 1.f / se;
                float dec[E_]; float mx2 = -1e30f;
                #pragma unroll
                for (int i = 0; i < E_; i++) {
                    float smi = smv[i] * inv;
                    float d = (lg[i] < kth) ? ALPHA * logf(smi + 1.f)
                                            : ALPHA * (expf(smi) - 1.f);
                    dec[i] = d; if (d > mx2) mx2 = d;
                }
                float s2 = 0.f;
                #pragma unroll
                for (int i = 0; i < E_; i++) { dec[i] = expf(dec[i] - mx2); s2 += dec[i]; }
                float inv2 = 1.f / s2;
                #pragma unroll
                for (int i = 0; i < E_; i++) g_gates[tok * E_ + i] = dec[i] * inv2;
            }
        }
        return;
    }

    // ---- gemm1 tile ----
    const int wid = tid >> 5, lane = tid & 31;
    const int g = lane >> 2, q = lane & 3;
    const int e = bid >> 8;
    const int r8 = bid & 255;
    const int bm = (r8 >> 4) * 128, bn = (r8 & 15) * 128;
    const int wm = (wid & 1) * 64, wn = (wid >> 1) * 32;
    const uint32_t smb = smem_u32(smh);

    const __half* gA = g_xf + (size_t)bm * S_;
    const __half* gB = g_w1t + ((size_t)e * H_ + bn) * S_;

    uint32_t aoff[4], boff[2];
    {
        const int lrA = lane & 15, lcA = ((lane >> 4) & 1) * 8;
        #pragma unroll
        for (int i = 0; i < 4; i++)
            aoff[i] = (uint32_t)(((wm + i * 16 + lrA) * PITCH + lcA) * 2);
        const int lrB = (lane & 7) + ((lane & 16) >> 1), lcB = lane & 8;
        #pragma unroll
        for (int p = 0; p < 2; p++)
            boff[p] = (uint32_t)(G1_B_OFF + ((wn + p * 16 + lrB) * PITCH + lcB) * 2);
    }

    float acc[4][4][4];
    #pragma unroll
    for (int i = 0; i < 4; i++)
        #pragma unroll
        for (int j = 0; j < 4; j++)
            #pragma unroll
            for (int c = 0; c < 4; c++) acc[i][j][c] = 0.f;

    auto load_stage = [&](int kt, int buf) {
        const uint32_t sA = smb + (uint32_t)buf * G1_STAGE_B;
        const uint32_t sB = sA + G1_B_OFF;
        const int k0 = kt * 32;
        #pragma unroll
        for (int i = 0; i < 2; i++) {
            int idx = tid + 256 * i;
            int r = idx >> 2, c = idx & 3;
            cp16(sA + (uint32_t)r * 80u + (uint32_t)c * 16u,
                 gA + (size_t)r * S_ + k0 + c * 8);
        }
        #pragma unroll
        for (int i = 0; i < 2; i++) {
            int idx = tid + 256 * i;
            int r = idx >> 2, c = idx & 3;
            cp16(sB + (uint32_t)r * 80u + (uint32_t)c * 16u,
                 gB + (size_t)r * S_ + k0 + c * 8);
        }
    };

    const int NKT = S_ / 32;   // 16
    #pragma unroll
    for (int s = 0; s < 3; s++) { load_stage(s, s); CP_COMMIT(); }

    for (int kt = 0; kt < NKT; kt++) {
        CP_WAIT2();
        __syncthreads();
        if (kt + 3 < NKT) load_stage(kt + 3, (kt + 3) & 3);
        CP_COMMIT();
        const uint32_t sbase = smb + (uint32_t)(kt & 3) * G1_STAGE_B;
        #pragma unroll
        for (int ks = 0; ks < 2; ks++) {
            const uint32_t kboff = (uint32_t)(ks * 16 * 2);
            uint32_t a[4][4], bf[2][4];
            #pragma unroll
            for (int i = 0; i < 4; i++) ldsm4(a[i], sbase + aoff[i] + kboff);
            #pragma unroll
            for (int p = 0; p < 2; p++) ldsm4(bf[p], sbase + boff[p] + kboff);
            #pragma unroll
            for (int i = 0; i < 4; i++)
                #pragma unroll
                for (int p = 0; p < 2; p++) {
                    mma16(acc[i][2 * p + 0], a[i], &bf[p][0]);
                    mma16(acc[i][2 * p + 1], a[i], &bf[p][2]);
                }
        }
    }

    const float* bias = b1 + (size_t)e * H_ + bn;
    #pragma unroll
    for (int i = 0; i < 4; i++) {
        int r0 = bm + wm + i * 16 + g;
        #pragma unroll
        for (int j = 0; j < 4; j++) {
            int col = wn + j * 8 + 2 * q;
            float bx = bias[col], by = bias[col + 1];
            __half2 o0 = __floats2half2_rn(gelu_f(acc[i][j][0] + bx),
                                           gelu_f(acc[i][j][1] + by));
            __half2 o1 = __floats2half2_rn(gelu_f(acc[i][j][2] + bx),
                                           gelu_f(acc[i][j][3] + by));
            *(__half2*)(g_h + ((size_t)e * T_ + r0) * H_ + bn + col) = o0;
            *(__half2*)(g_h + ((size_t)e * T_ + r0 + 8) * H_ + bn + col) = o1;
        }
    }
}

// ==================================================================
// 3) GEMM2 fused launch (1D grid 257):
//    [0,256)  gemm2 tiles (128x96x32, 5-stage, k-split x2)
//             epilogue: gated RED directly into out[b][f][p]
//             (ksp==0 folds in gate-weighted b2 bias)
//    256      losses
// ==================================================================
#define G2_STAGE_H ((128 + 96) * PITCH)
#define G2_B_OFF (128 * PITCH * 2)
#define G2_STAGE_B (G2_STAGE_H * 2)
#define G2_SMEM (5 * G2_STAGE_B)
__global__ void __launch_bounds__(256, 2) gemm2_fused(const float* __restrict__ b2,
                                                      float* __restrict__ out,
                                                      float* __restrict__ out_scalars) {
    extern __shared__ __half smh[];
    const int bid = blockIdx.x;
    const int tid = threadIdx.x;

    if (bid == 256) {
        // ---- losses: 256 threads, one (f,e) pair each ----
        __shared__ float gsum[F_][E_];
        __shared__ float cvf[F_], entf[F_];
        int f = tid >> 3, e = tid & 7;
        float s0 = 0.f, s1 = 0.f, s2 = 0.f, s3 = 0.f;
        #pragma unroll
        for (int b = 0; b < B_; b += 4) {
            s0 += g_gates[(f * B_ + b + 0) * E_ + e];
            s1 += g_gates[(f * B_ + b + 1) * E_ + e];
            s2 += g_gates[(f * B_ + b + 2) * E_ + e];
            s3 += g_gates[(f * B_ + b + 3) * E_ + e];
        }
        gsum[f][e] = (s0 + s1) + (s2 + s3);
        __syncthreads();
        if (tid < F_) {
            float mean = 0.f;
            #pragma unroll
            for (int i = 0; i < E_; i++) mean += gsum[tid][i];
            mean *= (1.f / E_);
            float ss = 0.f;
            #pragma unroll
            for (int i = 0; i < E_; i++) { float d = gsum[tid][i] - mean; ss += d * d; }
            float var = ss * (float)P_ / (float)(E_ * P_ - 1);
            cvf[tid] = var / (mean * mean + CV_EPS);
            float ent = 0.f;
            #pragma unroll
            for (int i = 0; i < E_; i++) {
                float g = gsum[tid][i] * (1.f / B_);
                ent += -g * logf(g + ENT_EPS);
            }
            entf[tid] = ent * (1.f / E_);
        }
        __syncthreads();
        if (tid == 0) {
            float a = 0.f, c = 0.f;
            for (int i = 0; i < F_; i++) { a += cvf[i]; c += entf[i]; }
            out_scalars[0] = a;
            out_scalars[1] = c;
        }
        return;
    }

    // ---- gemm2 tile ----
    const int wid = tid >> 5, lane = tid & 31;
    const int g = lane >> 2, q = lane & 3;
    const int ksp = bid & 1;
    const int bm = ((bid >> 1) & 15) * 128;
    const int e = bid >> 5;
    const int k_base = ksp * (H_ / KS2);
    const int wm = (wid & 3) * 32, wn = (wid >> 2) * 48;
    const uint32_t smb = smem_u32(smh);

    const __half* gA = g_h + ((size_t)e * T_ + bm) * H_ + k_base;
    const __half* gB = g_w2t + (size_t)e * P_ * H_ + k_base;

    uint32_t aoff[2], boff[3];
    {
        const int lrA = lane & 15, lcA = ((lane >> 4) & 1) * 8;
        #pragma unroll
        for (int i = 0; i < 2; i++)
            aoff[i] = (uint32_t)(((wm + i * 16 + lrA) * PITCH + lcA) * 2);
        const int lrB = (lane & 7) + ((lane & 16) >> 1), lcB = lane & 8;
        #pragma unroll
        for (int p = 0; p < 3; p++)
            boff[p] = (uint32_t)(G2_B_OFF + ((wn + p * 16 + lrB) * PITCH + lcB) * 2);
    }

    float acc[2][6][4];
    #pragma unroll
    for (int i = 0; i < 2; i++)
        #pragma unroll
        for (int j = 0; j < 6; j++)
            #pragma unroll
            for (int c = 0; c < 4; c++) acc[i][j][c] = 0.f;

    auto load_stage = [&](int kt, int buf) {
        const uint32_t sA = smb + (uint32_t)buf * G2_STAGE_B;
        const uint32_t sB = sA + G2_B_OFF;
        const int k0 = kt * 32;
        #pragma unroll
        for (int i = 0; i < 2; i++) {
            int idx = tid + 256 * i;
            int r = idx >> 2, c = idx & 3;
            cp16(sA + (uint32_t)r * 80u + (uint32_t)c * 16u,
                 gA + (size_t)r * H_ + k0 + c * 8);
        }
        #pragma unroll
        for (int i = 0; i < 2; i++) {
            int idx = tid + 256 * i;
            if (idx < 384) {
                int r = idx >> 2, c = idx & 3;
                cp16(sB + (uint32_t)r * 80u + (uint32_t)c * 16u,
                     gB + (size_t)r * H_ + k0 + c * 8);
            }
        }
    };

    const int NKT = (H_ / KS2) / 32;   // 32
    #pragma unroll
    for (int s = 0; s < 4; s++) { load_stage(s, s); CP_COMMIT(); }

    int buf = 0, pbuf = 4;
    for (int kt = 0; kt < NKT; kt++) {
        CP_WAIT3();
        __syncthreads();
        if (kt + 4 < NKT) load_stage(kt + 4, pbuf);
        CP_COMMIT();
        const uint32_t sbase = smb + (uint32_t)buf * G2_STAGE_B;
        #pragma unroll
        for (int ks = 0; ks < 2; ks++) {
            const uint32_t kboff = (uint32_t)(ks * 16 * 2);
            uint32_t a[2][4], bf[3][4];
            #pragma unroll
            for (int i = 0; i < 2; i++) ldsm4(a[i], sbase + aoff[i] + kboff);
            #pragma unroll
            for (int p = 0; p < 3; p++) ldsm4(bf[p], sbase + boff[p] + kboff);
            #pragma unroll
            for (int i = 0; i < 2; i++)
                #pragma unroll
                for (int p = 0; p < 3; p++) {
                    mma16(acc[i][2 * p + 0], a[i], &bf[p][0]);
                    mma16(acc[i][2 * p + 1], a[i], &bf[p][2]);
                }
        }
        buf = (buf == 4) ? 0 : buf + 1;
        pbuf = (pbuf == 4) ? 0 : pbuf + 1;
    }

    // epilogue: gated RED directly into out[b][f][p]; ksp==0 adds bias
    const float* bias = b2 + e * P_;
    #pragma unroll
    for (int i = 0; i < 2; i++) {
        int t0 = bm + wm + i * 16 + g;
        int t8 = t0 + 8;
        float gt0 = g_gates[t0 * E_ + e];
        float gt8 = g_gates[t8 * E_ + e];
        float* o0 = out + ((size_t)(t0 & 63) * F_ + (t0 >> 6)) * P_;
        float* o8 = out + ((size_t)(t8 & 63) * F_ + (t8 >> 6)) * P_;
        #pragma unroll
        for (int j = 0; j < 6; j++) {
            int col = wn + j * 8 + 2 * q;
            float bx = (ksp == 0) ? bias[col] : 0.f;
            float by = (ksp == 0) ? bias[col + 1] : 0.f;
            atomicAdd(o0 + col,     gt0 * (acc[i][j][0] + bx));
            atomicAdd(o0 + col + 1, gt0 * (acc[i][j][1] + by));
            atomicAdd(o8 + col,     gt8 * (acc[i][j][2] + bx));
            atomicAdd(o8 + col + 1, gt8 * (acc[i][j][3] + by));
        }
    }
}

// ==================================================================
extern "C" void kernel_launch(void* const* d_in, const int* in_sizes, int n_in,
                              void* d_out, int out_size) {
    const float* x  = (const float*)d_in[0];
    const float* te = (const float*)d_in[1];
    const float* Wg = (const float*)d_in[2];
    const float* bg = (const float*)d_in[3];
    const float* W1 = (const float*)d_in[4];
    const float* b1 = (const float*)d_in[5];
    const float* W2 = (const float*)d_in[6];
    const float* b2 = (const float*)d_in[7];
    float* out = (float*)d_out;

    cudaFuncSetAttribute(gemm1_fused, cudaFuncAttributeMaxDynamicSharedMemorySize, G1_SMEM);
    cudaFuncSetAttribute(gemm2_fused, cudaFuncAttributeMaxDynamicSharedMemorySize, G2_SMEM);

    prep_xw<<<PREP_TOTAL, 256>>>(x, W1);
    gemm1_fused<<<G1_TOTAL, 256, G1_SMEM>>>(b1, W2, te, Wg, bg, out);
    gemm2_fused<<<257, 256, G2_SMEM>>>(b2, out, out + (out_size - 2));
}

// round 13
// speedup vs baseline: 1.0642x; 1.0109x over previous
#include <cuda_runtime.h>
#include <cuda_fp16.h>
#include <math.h>
#include <stdint.h>

#define B_ 64
#define F_ 32
#define S_ 512
#define P_ 96
#define E_ 8
#define H_ 2048
#define T_ (F_*B_)   /* 2048 tokens */
#define ALPHA 10.0f
#define ENT_EPS 1e-8f
#define CV_EPS 1e-10f
#define KS2 2        /* gemm2 k-split */

// ---- scratch (device globals: allocation-free) ----
__device__ __half g_xf[(size_t)T_ * S_];           // 2 MB   token-major x (fp16)
__device__ __half g_w1t[(size_t)E_ * H_ * S_];     // 16.8MB W1^T [e][h][s] (fp16)
__device__ __half g_w2t[(size_t)E_ * P_ * H_];     // 3.1 MB W2^T [e][p][h] (fp16)
__device__ float  g_gates[T_ * E_];                // 64 KB
__device__ __half g_h[(size_t)E_ * T_ * H_];       // 67 MB  gelu(x@W1+b1) (fp16)

// ==================================================================
// helpers
// ==================================================================
__device__ __forceinline__ uint32_t smem_u32(const void* p) {
    uint32_t a;
    asm("{ .reg .u64 t; cvta.to.shared.u64 t, %1; cvt.u32.u64 %0, t; }"
        : "=r"(a) : "l"(p));
    return a;
}
__device__ __forceinline__ void cp16(uint32_t saddr, const void* gaddr) {
    asm volatile("cp.async.cg.shared.global [%0], [%1], 16;"
                 :: "r"(saddr), "l"(gaddr) : "memory");
}
#define CP_COMMIT() asm volatile("cp.async.commit_group;" ::: "memory")
#define CP_WAIT2()  asm volatile("cp.async.wait_group 2;" ::: "memory")
#define CP_WAIT3()  asm volatile("cp.async.wait_group 3;" ::: "memory")

__device__ __forceinline__ void mma16(float* d, const uint32_t* a, const uint32_t* b) {
    asm volatile(
        "mma.sync.aligned.m16n8k16.row.col.f32.f16.f16.f32 "
        "{%0,%1,%2,%3}, {%4,%5,%6,%7}, {%8,%9}, {%0,%1,%2,%3};"
        : "+f"(d[0]), "+f"(d[1]), "+f"(d[2]), "+f"(d[3])
        : "r"(a[0]), "r"(a[1]), "r"(a[2]), "r"(a[3]), "r"(b[0]), "r"(b[1]));
}
__device__ __forceinline__ void ldsm4(uint32_t* r, uint32_t addr) {
    asm volatile("ldmatrix.sync.aligned.m8n8.x4.shared.b16 {%0,%1,%2,%3}, [%4];"
                 : "=r"(r[0]), "=r"(r[1]), "=r"(r[2]), "=r"(r[3]) : "r"(addr));
}
__device__ __forceinline__ float gelu_f(float v) {
    return 0.5f * v * (1.f + erff(v * 0.70710678118f));
}
__device__ __forceinline__ uint32_t pack_h2(float a, float b) {
    __half2 h = __floats2half2_rn(a, b);
    return *(uint32_t*)&h;
}

// smem pitch: 40 halves (80 B) per 32-half row -> conflict-free (scalar + ldmatrix)
#define PITCH 40

// ==================================================================
// 1) prep: x->g_xf (blocks [0,512), 4 tokens each),
//          W1^T (blocks [512,4608), 64s x 32h tiles, vectorized)
// ==================================================================
#define PREP_XF_BLKS 512
#define PREP_W1_BLKS (8 * 64 * E_)      /* 4096 */
#define PREP_TOTAL (PREP_XF_BLKS + PREP_W1_BLKS)
__global__ void __launch_bounds__(256) prep_xw(const float* __restrict__ x,
                                               const float* __restrict__ W1) {
    __shared__ float tile[64 * 33];
    int bid = blockIdx.x;
    const int tid = threadIdx.x;
    if (bid < PREP_XF_BLKS) {
        int t = bid * 4 + (tid >> 6);
        int l64 = tid & 63;
        int f = t / B_, b = t - f * B_;
        const float4* src = (const float4*)(x + ((size_t)b * F_ + f) * S_);
        float4 v0 = src[l64 * 2];
        float4 v1 = src[l64 * 2 + 1];
        uint4 o;
        o.x = pack_h2(v0.x, v0.y);
        o.y = pack_h2(v0.z, v0.w);
        o.z = pack_h2(v1.x, v1.y);
        o.w = pack_h2(v1.z, v1.w);
        *(uint4*)(g_xf + (size_t)t * S_ + l64 * 8) = o;
    } else {
        // W1^T: 64s x 32h tile
        int i = bid - PREP_XF_BLKS;
        int e = i >> 9;                  // 512 tiles per expert
        int r = i & 511;
        int s0 = (r >> 6) * 64, h0 = (r & 63) * 32;
        // load: 2x LDG.128 per thread
        {
            int s = tid >> 2, c0 = (tid & 3) * 8;
            const float4* src = (const float4*)(W1 + ((size_t)e * S_ + s0 + s) * H_ + h0 + c0);
            float4 v0 = src[0], v1 = src[1];
            float* tp = tile + s * 33 + c0;
            tp[0] = v0.x; tp[1] = v0.y; tp[2] = v0.z; tp[3] = v0.w;
            tp[4] = v1.x; tp[5] = v1.y; tp[6] = v1.z; tp[7] = v1.w;
        }
        __syncthreads();
        // write: 1x STG.128 of 8 halves per thread
        {
            int w = tid >> 5, l = tid & 31;
            int hrow = w * 4 + (l >> 3);         // 0..31
            int sc = (l & 7) * 8;                // 0..56
            uint4 o;
            o.x = pack_h2(tile[(sc + 0) * 33 + hrow], tile[(sc + 1) * 33 + hrow]);
            o.y = pack_h2(tile[(sc + 2) * 33 + hrow], tile[(sc + 3) * 33 + hrow]);
            o.z = pack_h2(tile[(sc + 4) * 33 + hrow], tile[(sc + 5) * 33 + hrow]);
            o.w = pack_h2(tile[(sc + 6) * 33 + hrow], tile[(sc + 7) * 33 + hrow]);
            *(uint4*)(g_w1t + ((size_t)e * H_ + h0 + hrow) * S_ + s0 + sc) = o;
        }
    }
}

// ==================================================================
// 2) GEMM1 fused launch (1D grid):
//    [0, 2048)      gemm1 HMMA tiles (128x128x32, 4-stage, 8 warps)
//    [2048, 2816)   W2^T transpose (32p x 64h, vectorized)
//    [2816, 3008)   zero out[0, T*P)
//    [3008, 3264)   gates (8 tokens per block)
// ==================================================================
#define G1_TILES 2048
#define G1_W2_END (G1_TILES + 768)
#define G1_ZERO_END (G1_W2_END + 192)
#define G1_TOTAL (G1_ZERO_END + 256)
#define G1_B_OFF (128 * PITCH * 2)                  /* bytes */
#define G1_STAGE_B (2 * 128 * PITCH * 2)            /* 20480 bytes */
#define G1_SMEM (4 * G1_STAGE_B)
__global__ void __launch_bounds__(256, 2) gemm1_fused(const float* __restrict__ b1,
                                                      const float* __restrict__ W2,
                                                      const float* __restrict__ te,
                                                      const float* __restrict__ Wg,
                                                      const float* __restrict__ bg,
                                                      float* __restrict__ out) {
    extern __shared__ __half smh[];
    const int bid = blockIdx.x;
    const int tid = threadIdx.x;

    if (bid >= G1_TILES) {
        if (bid < G1_W2_END) {
            // ---- W2^T: 32p x 64h tile, transposed smem (pitch 65) ----
            float* tile = (float*)smh;               // 32*65 floats = 8.3 KB
            int i = bid - G1_TILES;
            int e = i / 96, r = i % 96;
            int p0 = (r % 3) * 32, h0 = (r / 3) * 64;
            {
                int hr = tid >> 2, pc = (tid & 3) * 8;
                const float4* src = (const float4*)(W2 + ((size_t)e * H_ + h0 + hr) * P_ + p0 + pc);
                float4 v0 = src[0], v1 = src[1];
                tile[(pc + 0) * 65 + hr] = v0.x;
                tile[(pc + 1) * 65 + hr] = v0.y;
                tile[(pc + 2) * 65 + hr] = v0.z;
                tile[(pc + 3) * 65 + hr] = v0.w;
                tile[(pc + 4) * 65 + hr] = v1.x;
                tile[(pc + 5) * 65 + hr] = v1.y;
                tile[(pc + 6) * 65 + hr] = v1.z;
                tile[(pc + 7) * 65 + hr] = v1.w;
            }
            __syncthreads();
            {
                int w = tid >> 5, l = tid & 31;
                int p = w * 4 + (l >> 3);            // 0..31
                int sc = (l & 7) * 8;                // h offset 0..56
                const float* tp = tile + p * 65 + sc;
                uint4 o;
                o.x = pack_h2(tp[0], tp[1]);
                o.y = pack_h2(tp[2], tp[3]);
                o.z = pack_h2(tp[4], tp[5]);
                o.w = pack_h2(tp[6], tp[7]);
                *(uint4*)(g_w2t + ((size_t)e * P_ + p0 + p) * H_ + h0 + sc) = o;
            }
        } else if (bid < G1_ZERO_END) {
            int i = bid - G1_W2_END;
            ((float4*)out)[i * 256 + tid] = make_float4(0.f, 0.f, 0.f, 0.f);
        } else {
            // ---- gates: 8 tokens, one warp per token ----
            float* s_wg = (float*)smh;               // [512][9] = 18 KB
            #pragma unroll
            for (int k = 0; k < 16; k++) {
                int idx = tid + 256 * k;             // 4096
                s_wg[(idx >> 3) * 9 + (idx & 7)] = Wg[idx];
            }
            __syncthreads();

            const int w = tid >> 5, lane = tid & 31;
            const int tok = (bid - G1_ZERO_END) * 8 + w;
            const int f = tok / B_, b = tok - f * B_;
            const float* row = te + ((size_t)b * F_ + f) * S_;

            float acc[E_];
            #pragma unroll
            for (int e = 0; e < E_; e++) acc[e] = 0.f;
            #pragma unroll
            for (int c = 0; c < 16; c++) {
                float v = row[c * 32 + lane];
                const float* wp = s_wg + (c * 32 + lane) * 9;
                #pragma unroll
                for (int e = 0; e < E_; e++) acc[e] += v * wp[e];
            }
            #pragma unroll
            for (int e = 0; e < E_; e++)
                #pragma unroll
                for (int o = 16; o > 0; o >>= 1)
                    acc[e] += __shfl_xor_sync(0xffffffffu, acc[e], o);

            if (lane == 0) {
                float lg[E_];
                float m1 = -1e30f, m2 = -1e30f;
                #pragma unroll
                for (int i = 0; i < E_; i++) {
                    float v = acc[i] + bg[i]; lg[i] = v;
                    if (v > m1) { m2 = m1; m1 = v; } else if (v > m2) m2 = v;
                }
                float kth = m2;
                float smv[E_]; float se = 0.f;
                #pragma unroll
                for (int i = 0; i < E_; i++) { smv[i] = expf(lg[i] - m1); se += smv[i]; }
                float inv = 1.f / se;
                float dec[E_]; float mx2 = -1e30f;
                #pragma unroll
                for (int i = 0; i < E_; i++) {
                    float smi = smv[i] * inv;
                    float d = (lg[i] < kth) ? ALPHA * logf(smi + 1.f)
                                            : ALPHA * (expf(smi) - 1.f);
                    dec[i] = d; if (d > mx2) mx2 = d;
                }
                float s2 = 0.f;
                #pragma unroll
                for (int i = 0; i < E_; i++) { dec[i] = expf(dec[i] - mx2); s2 += dec[i]; }
                float inv2 = 1.f / s2;
                #pragma unroll
                for (int i = 0; i < E_; i++) g_gates[tok * E_ + i] = dec[i] * inv2;
            }
        }
        return;
    }

    // ---- gemm1 tile ----
    const int wid = tid >> 5, lane = tid & 31;
    const int g = lane >> 2, q = lane & 3;
    const int e = bid >> 8;
    const int r8 = bid & 255;
    const int bm = (r8 >> 4) * 128, bn = (r8 & 15) * 128;
    const int wm = (wid & 1) * 64, wn = (wid >> 1) * 32;
    const uint32_t smb = smem_u32(smh);

    const __half* gA = g_xf + (size_t)bm * S_;
    const __half* gB = g_w1t + ((size_t)e * H_ + bn) * S_;

    uint32_t aoff[4], boff[2];
    {
        const int lrA = lane & 15, lcA = ((lane >> 4) & 1) * 8;
        #pragma unroll
        for (int i = 0; i < 4; i++)
            aoff[i] = (uint32_t)(((wm + i * 16 + lrA) * PITCH + lcA) * 2);
        const int lrB = (lane & 7) + ((lane & 16) >> 1), lcB = lane & 8;
        #pragma unroll
        for (int p = 0; p < 2; p++)
            boff[p] = (uint32_t)(G1_B_OFF + ((wn + p * 16 + lrB) * PITCH + lcB) * 2);
    }

    float acc[4][4][4];
    #pragma unroll
    for (int i = 0; i < 4; i++)
        #pragma unroll
        for (int j = 0; j < 4; j++)
            #pragma unroll
            for (int c = 0; c < 4; c++) acc[i][j][c] = 0.f;

    auto load_stage = [&](int kt, int buf) {
        const uint32_t sA = smb + (uint32_t)buf * G1_STAGE_B;
        const uint32_t sB = sA + G1_B_OFF;
        const int k0 = kt * 32;
        #pragma unroll
        for (int i = 0; i < 2; i++) {
            int idx = tid + 256 * i;
            int r = idx >> 2, c = idx & 3;
            cp16(sA + (uint32_t)r * 80u + (uint32_t)c * 16u,
                 gA + (size_t)r * S_ + k0 + c * 8);
        }
        #pragma unroll
        for (int i = 0; i < 2; i++) {
            int idx = tid + 256 * i;
            int r = idx >> 2, c = idx & 3;
            cp16(sB + (uint32_t)r * 80u + (uint32_t)c * 16u,
                 gB + (size_t)r * S_ + k0 + c * 8);
        }
    };

    const int NKT = S_ / 32;   // 16
    #pragma unroll
    for (int s = 0; s < 3; s++) { load_stage(s, s); CP_COMMIT(); }

    for (int kt = 0; kt < NKT; kt++) {
        CP_WAIT2();
        __syncthreads();
        if (kt + 3 < NKT) load_stage(kt + 3, (kt + 3) & 3);
        CP_COMMIT();
        const uint32_t sbase = smb + (uint32_t)(kt & 3) * G1_STAGE_B;
        #pragma unroll
        for (int ks = 0; ks < 2; ks++) {
            const uint32_t kboff = (uint32_t)(ks * 16 * 2);
            uint32_t a[4][4], bf[2][4];
            #pragma unroll
            for (int i = 0; i < 4; i++) ldsm4(a[i], sbase + aoff[i] + kboff);
            #pragma unroll
            for (int p = 0; p < 2; p++) ldsm4(bf[p], sbase + boff[p] + kboff);
            #pragma unroll
            for (int i = 0; i < 4; i++)
                #pragma unroll
                for (int p = 0; p < 2; p++) {
                    mma16(acc[i][2 * p + 0], a[i], &bf[p][0]);
                    mma16(acc[i][2 * p + 1], a[i], &bf[p][2]);
                }
        }
    }

    const float* bias = b1 + (size_t)e * H_ + bn;
    #pragma unroll
    for (int i = 0; i < 4; i++) {
        int r0 = bm + wm + i * 16 + g;
        #pragma unroll
        for (int j = 0; j < 4; j++) {
            int col = wn + j * 8 + 2 * q;
            float bx = bias[col], by = bias[col + 1];
            __half2 o0 = __floats2half2_rn(gelu_f(acc[i][j][0] + bx),
                                           gelu_f(acc[i][j][1] + by));
            __half2 o1 = __floats2half2_rn(gelu_f(acc[i][j][2] + bx),
                                           gelu_f(acc[i][j][3] + by));
            *(__half2*)(g_h + ((size_t)e * T_ + r0) * H_ + bn + col) = o0;
            *(__half2*)(g_h + ((size_t)e * T_ + r0 + 8) * H_ + bn + col) = o1;
        }
    }
}

// ==================================================================
// 3) GEMM2 fused launch (1D grid 257):
//    [0,256)  gemm2 tiles (128x96x32, 5-stage, k-split x2)
//             epilogue: gated RED directly into out[b][f][p]
//    256      losses
// ==================================================================
#define G2_STAGE_H ((128 + 96) * PITCH)
#define G2_B_OFF (128 * PITCH * 2)
#define G2_STAGE_B (G2_STAGE_H * 2)
#define G2_SMEM (5 * G2_STAGE_B)
__global__ void __launch_bounds__(256, 2) gemm2_fused(const float* __restrict__ b2,
                                                      float* __restrict__ out,
                                                      float* __restrict__ out_scalars) {
    extern __shared__ __half smh[];
    const int bid = blockIdx.x;
    const int tid = threadIdx.x;

    if (bid == 256) {
        // ---- losses ----
        __shared__ float gsum[F_][E_];
        __shared__ float cvf[F_], entf[F_];
        int f = tid >> 3, e = tid & 7;
        float s0 = 0.f, s1 = 0.f, s2 = 0.f, s3 = 0.f;
        #pragma unroll
        for (int b = 0; b < B_; b += 4) {
            s0 += g_gates[(f * B_ + b + 0) * E_ + e];
            s1 += g_gates[(f * B_ + b + 1) * E_ + e];
            s2 += g_gates[(f * B_ + b + 2) * E_ + e];
            s3 += g_gates[(f * B_ + b + 3) * E_ + e];
        }
        gsum[f][e] = (s0 + s1) + (s2 + s3);
        __syncthreads();
        if (tid < F_) {
            float mean = 0.f;
            #pragma unroll
            for (int i = 0; i < E_; i++) mean += gsum[tid][i];
            mean *= (1.f / E_);
            float ss = 0.f;
            #pragma unroll
            for (int i = 0; i < E_; i++) { float d = gsum[tid][i] - mean; ss += d * d; }
            float var = ss * (float)P_ / (float)(E_ * P_ - 1);
            cvf[tid] = var / (mean * mean + CV_EPS);
            float ent = 0.f;
            #pragma unroll
            for (int i = 0; i < E_; i++) {
                float g = gsum[tid][i] * (1.f / B_);
                ent += -g * logf(g + ENT_EPS);
            }
            entf[tid] = ent * (1.f / E_);
        }
        __syncthreads();
        if (tid == 0) {
            float a = 0.f, c = 0.f;
            for (int i = 0; i < F_; i++) { a += cvf[i]; c += entf[i]; }
            out_scalars[0] = a;
            out_scalars[1] = c;
        }
        return;
    }

    // ---- gemm2 tile ----
    const int wid = tid >> 5, lane = tid & 31;
    const int g = lane >> 2, q = lane & 3;
    const int ksp = bid & 1;
    const int bm = ((bid >> 1) & 15) * 128;
    const int e = bid >> 5;
    const int k_base = ksp * (H_ / KS2);
    const int wm = (wid & 3) * 32, wn = (wid >> 2) * 48;
    const uint32_t smb = smem_u32(smh);

    const __half* gA = g_h + ((size_t)e * T_ + bm) * H_ + k_base;
    const __half* gB = g_w2t + (size_t)e * P_ * H_ + k_base;

    uint32_t aoff[2], boff[3];
    {
        const int lrA = lane & 15, lcA = ((lane >> 4) & 1) * 8;
        #pragma unroll
        for (int i = 0; i < 2; i++)
            aoff[i] = (uint32_t)(((wm + i * 16 + lrA) * PITCH + lcA) * 2);
        const int lrB = (lane & 7) + ((lane & 16) >> 1), lcB = lane & 8;
        #pragma unroll
        for (int p = 0; p < 3; p++)
            boff[p] = (uint32_t)(G2_B_OFF + ((wn + p * 16 + lrB) * PITCH + lcB) * 2);
    }

    float acc[2][6][4];
    #pragma unroll
    for (int i = 0; i < 2; i++)
        #pragma unroll
        for (int j = 0; j < 6; j++)
            #pragma unroll
            for (int c = 0; c < 4; c++) acc[i][j][c] = 0.f;

    auto load_stage = [&](int kt, int buf) {
        const uint32_t sA = smb + (uint32_t)buf * G2_STAGE_B;
        const uint32_t sB = sA + G2_B_OFF;
        const int k0 = kt * 32;
        #pragma unroll
        for (int i = 0; i < 2; i++) {
            int idx = tid + 256 * i;
            int r = idx >> 2, c = idx & 3;
            cp16(sA + (uint32_t)r * 80u + (uint32_t)c * 16u,
                 gA + (size_t)r * H_ + k0 + c * 8);
        }
        #pragma unroll
        for (int i = 0; i < 2; i++) {
            int idx = tid + 256 * i;
            if (idx < 384) {
                int r = idx >> 2, c = idx & 3;
                cp16(sB + (uint32_t)r * 80u + (uint32_t)c * 16u,
                     gB + (size_t)r * H_ + k0 + c * 8);
            }
        }
    };

    const int NKT = (H_ / KS2) / 32;   // 32
    #pragma unroll
    for (int s = 0; s < 4; s++) { load_stage(s, s); CP_COMMIT(); }

    int buf = 0, pbuf = 4;
    for (int kt = 0; kt < NKT; kt++) {
        CP_WAIT3();
        __syncthreads();
        if (kt + 4 < NKT) load_stage(kt + 4, pbuf);
        CP_COMMIT();
        const uint32_t sbase = smb + (uint32_t)buf * G2_STAGE_B;
        #pragma unroll
        for (int ks = 0; ks < 2; ks++) {
            const uint32_t kboff = (uint32_t)(ks * 16 * 2);
            uint32_t a[2][4], bf[3][4];
            #pragma unroll
            for (int i = 0; i < 2; i++) ldsm4(a[i], sbase + aoff[i] + kboff);
            #pragma unroll
            for (int p = 0; p < 3; p++) ldsm4(bf[p], sbase + boff[p] + kboff);
            #pragma unroll
            for (int i = 0; i < 2; i++)
                #pragma unroll
                for (int p = 0; p < 3; p++) {
                    mma16(acc[i][2 * p + 0], a[i], &bf[p][0]);
                    mma16(acc[i][2 * p + 1], a[i], &bf[p][2]);
                }
        }
        buf = (buf == 4) ? 0 : buf + 1;
        pbuf = (pbuf == 4) ? 0 : pbuf + 1;
    }

    // epilogue: gated RED directly into out[b][f][p]; ksp==0 adds bias
    const float* bias = b2 + e * P_;
    #pragma unroll
    for (int i = 0; i < 2; i++) {
        int t0 = bm + wm + i * 16 + g;
        int t8 = t0 + 8;
        float gt0 = g_gates[t0 * E_ + e];
        float gt8 = g_gates[t8 * E_ + e];
        float* o0 = out + ((size_t)(t0 & 63) * F_ + (t0 >> 6)) * P_;
        float* o8 = out + ((size_t)(t8 & 63) * F_ + (t8 >> 6)) * P_;
        #pragma unroll
        for (int j = 0; j < 6; j++) {
            int col = wn + j * 8 + 2 * q;
            float bx = (ksp == 0) ? bias[col] : 0.f;
            float by = (ksp == 0) ? bias[col + 1] : 0.f;
            atomicAdd(o0 + col,     gt0 * (acc[i][j][0] + bx));
            atomicAdd(o0 + col + 1, gt0 * (acc[i][j][1] + by));
            atomicAdd(o8 + col,     gt8 * (acc[i][j][2] + bx));
            atomicAdd(o8 + col + 1, gt8 * (acc[i][j][3] + by));
        }
    }
}

// ==================================================================
extern "C" void kernel_launch(void* const* d_in, const int* in_sizes, int n_in,
                              void* d_out, int out_size) {
    const float* x  = (const float*)d_in[0];
    const float* te = (const float*)d_in[1];
    const float* Wg = (const float*)d_in[2];
    const float* bg = (const float*)d_in[3];
    const float* W1 = (const float*)d_in[4];
    const float* b1 = (const float*)d_in[5];
    const float* W2 = (const float*)d_in[6];
    const float* b2 = (const float*)d_in[7];
    float* out = (float*)d_out;

    cudaFuncSetAttribute(gemm1_fused, cudaFuncAttributeMaxDynamicSharedMemorySize, G1_SMEM);
    cudaFuncSetAttribute(gemm2_fused, cudaFuncAttributeMaxDynamicSharedMemorySize, G2_SMEM);

    prep_xw<<<PREP_TOTAL, 256>>>(x, W1);
    gemm1_fused<<<G1_TOTAL, 256, G1_SMEM>>>(b1, W2, te, Wg, bg, out);
    gemm2_fused<<<257, 256, G2_SMEM>>>(b2, out, out + (out_size - 2));
}